// round 7
// baseline (speedup 1.0000x reference)
#include <cuda_runtime.h>
#include <cuda_bf16.h>
#include <math_constants.h>
#include <stdint.h>

// Problem constants
#define BATCH   96
#define NW      10
#define NTOK    144            // window tokens
#define CDIM    192
#define HEADS   6
#define DH      32
#define MTOT    (BATCH*NW*NTOK)        // 138240
#define NHEADTOT (BATCH*NW*HEADS)      // 5760
#define NN2     (NTOK*NTOK)            // 20736
#define BIASTOT (NW*HEADS*NN2)         // 1244160
#define QKVN    (3*CDIM)               // 576
#define SCALE   0.17677669529663687f   // 32^-0.5

// ---------------- packed f32x2 helpers (Blackwell family FFMA2) ------------
__device__ __forceinline__ unsigned long long pack2(float lo, float hi) {
    unsigned long long r;
    asm("mov.b64 %0, {%1, %2};" : "=l"(r) : "f"(lo), "f"(hi));
    return r;
}
__device__ __forceinline__ float2 unpack2(unsigned long long v) {
    float2 f;
    asm("mov.b64 {%0, %1}, %2;" : "=f"(f.x), "=f"(f.y) : "l"(v));
    return f;
}
__device__ __forceinline__ unsigned long long fma2(unsigned long long a,
                                                   unsigned long long b,
                                                   unsigned long long c) {
    unsigned long long d;
    asm("fma.rn.f32x2 %0, %1, %2, %3;" : "=l"(d) : "l"(a), "l"(b), "l"(c));
    return d;
}
__device__ __forceinline__ unsigned long long mul2(unsigned long long a,
                                                   unsigned long long b) {
    unsigned long long d;
    asm("mul.rn.f32x2 %0, %1, %2;" : "=l"(d) : "l"(a), "l"(b));
    return d;
}
__device__ __forceinline__ unsigned long long add2(unsigned long long a,
                                                   unsigned long long b) {
    unsigned long long d;
    asm("add.rn.f32x2 %0, %1, %2;" : "=l"(d) : "l"(a), "l"(b));
    return d;
}
__device__ __forceinline__ unsigned long long d_as_ull(double x) {
    return __double_as_longlong(x);
}

// -------- scratch (device globals; no runtime allocation allowed) ----------
__device__ float g_q[NHEADTOT * NTOK * DH];   // [head][n][d], pre-scaled
__device__ float g_k[NHEADTOT * NTOK * DH];
__device__ float g_v[NHEADTOT * NTOK * DH];
__device__ float g_att[MTOT * CDIM];          // attention output, [B,nW,N,C]
__device__ float g_bias[BIASTOT];             // [w][h][i*N+j]

// ---------------------------------------------------------------------------
// K0: materialize relative-position bias
// ---------------------------------------------------------------------------
__global__ void build_bias_kernel(const float* __restrict__ bias_table,
                                  const int* __restrict__ pidx) {
    int idx = blockIdx.x * blockDim.x + threadIdx.x;
    if (idx >= BIASTOT) return;
    int wh = idx / NN2;
    int ij = idx - wh * NN2;
    g_bias[idx] = bias_table[pidx[ij] * (NW * HEADS) + wh];
}

// ---------------------------------------------------------------------------
// K1: QKV GEMM  X[M,192] @ W[192,576] + b  -> scatter to g_q/g_k/g_v
// FFMA2 inner loop: accumulators packed along m (pairs), b replicated.
// ---------------------------------------------------------------------------
#define GBM 128
#define GBN 64
#define GBK 16

__global__ __launch_bounds__(256)
void qkv_gemm_kernel(const float* __restrict__ X,
                     const float* __restrict__ W,
                     const float* __restrict__ bqkv) {
    __shared__ float As[GBK][GBM];
    __shared__ float Bs[GBK][GBN];

    const int m0 = blockIdx.x * GBM;
    const int n0 = blockIdx.y * GBN;
    const int tid = threadIdx.x;
    const int tx = tid & 15;       // 0..15 col group
    const int ty = tid >> 4;       // 0..15 row group

    // cp[i][j]: lanes = rows (ty*8+2i, ty*8+2i+1), col j
    unsigned long long cp[4][4];
    #pragma unroll
    for (int i = 0; i < 4; ++i)
        #pragma unroll
        for (int j = 0; j < 4; ++j) cp[i][j] = 0ull;

    for (int k0 = 0; k0 < CDIM; k0 += GBK) {
        // ---- load A tile (128 rows x 16 k) : 512 float4, 2 per thread ----
        #pragma unroll
        for (int l = 0; l < 2; ++l) {
            int idx = tid + l * 256;
            int row = idx >> 2;
            int c4  = idx & 3;
            float4 a = *(const float4*)(X + (size_t)(m0 + row) * CDIM + k0 + c4 * 4);
            As[c4 * 4 + 0][row] = a.x;
            As[c4 * 4 + 1][row] = a.y;
            As[c4 * 4 + 2][row] = a.z;
            As[c4 * 4 + 3][row] = a.w;
        }
        // ---- load B tile (16 k x 64 n): 256 float4, 1 per thread ----
        {
            int krow = tid >> 4;
            int c4   = tid & 15;
            *(float4*)&Bs[krow][c4 * 4] =
                *(const float4*)(W + (size_t)(k0 + krow) * QKVN + n0 + c4 * 4);
        }
        __syncthreads();

        #pragma unroll
        for (int k = 0; k < GBK; ++k) {
            const double2* ap = (const double2*)&As[k][ty * 8];
            double2 a01 = ap[0], a23 = ap[1];
            unsigned long long apair[4] = {
                d_as_ull(a01.x), d_as_ull(a01.y),
                d_as_ull(a23.x), d_as_ull(a23.y)};
            float4 bb = *(const float4*)&Bs[k][tx * 4];
            unsigned long long br[4] = {
                pack2(bb.x, bb.x), pack2(bb.y, bb.y),
                pack2(bb.z, bb.z), pack2(bb.w, bb.w)};
            #pragma unroll
            for (int i = 0; i < 4; ++i)
                #pragma unroll
                for (int j = 0; j < 4; ++j)
                    cp[i][j] = fma2(apair[i], br[j], cp[i][j]);
        }
        __syncthreads();
    }

    // ---- epilogue: unpack, bias add + scatter to q/k/v ----
    const int cg = n0 + tx * 4;            // column (multiple of 4, within one head)
    const int t  = cg / CDIM;              // 0=q,1=k,2=v
    const int rem = cg - t * CDIM;
    const int h  = rem >> 5;
    const int d  = rem & 31;
    float* dstbase = (t == 0) ? g_q : (t == 1) ? g_k : g_v;
    const float sc = (t == 0) ? SCALE : 1.0f;
    float4 bq = *(const float4*)(bqkv + cg);

    #pragma unroll
    for (int i = 0; i < 4; ++i) {
        float2 f0 = unpack2(cp[i][0]);
        float2 f1 = unpack2(cp[i][1]);
        float2 f2 = unpack2(cp[i][2]);
        float2 f3 = unpack2(cp[i][3]);
        #pragma unroll
        for (int half = 0; half < 2; ++half) {
            int m  = m0 + ty * 8 + 2 * i + half;
            int bw = m / NTOK;
            int nn = m - bw * NTOK;
            float4 val;
            val.x = ((half ? f0.y : f0.x) + bq.x) * sc;
            val.y = ((half ? f1.y : f1.x) + bq.y) * sc;
            val.z = ((half ? f2.y : f2.x) + bq.z) * sc;
            val.w = ((half ? f3.y : f3.x) + bq.w) * sc;
            *(float4*)&dstbase[(size_t)((bw * HEADS + h) * NTOK + nn) * DH + d] = val;
        }
    }
}

// ---------------------------------------------------------------------------
// K2: fused attention, one block per (b,w,h) head. FFMA2 inner loops.
// ---------------------------------------------------------------------------
__global__ __launch_bounds__(160)
void attn_kernel(const float* __restrict__ mask) {
    __shared__ float Ks[NTOK * DH];        // 18432 B
    __shared__ float Vs[NTOK * DH];        // 18432 B
    __shared__ float BMs[NTOK * 17];       // 9792 B

    const int head = blockIdx.x;
    const int h    = head % HEADS;
    const int bw   = head / HEADS;
    const int b    = head / (NW * HEADS);
    const int t    = threadIdx.x;

    const float* kb = g_k + (size_t)head * NTOK * DH;
    const float* vb = g_v + (size_t)head * NTOK * DH;
    const float* qb = g_q + (size_t)head * NTOK * DH;
    const float* biasWH = g_bias + (size_t)(head % (NW * HEADS)) * NN2;
    const float* maskB  = mask + (size_t)b * NN2;

    // cooperative K/V load (coalesced float4)
    for (int idx = t; idx < NTOK * DH / 4; idx += 160) {
        ((float4*)Ks)[idx] = ((const float4*)kb)[idx];
        ((float4*)Vs)[idx] = ((const float4*)vb)[idx];
    }

    // per-thread q row, packed into d-pairs
    unsigned long long qp[16];
    if (t < NTOK) {
        const float4* qr = (const float4*)(qb + t * DH);
        #pragma unroll
        for (int d4 = 0; d4 < 8; ++d4) {
            float4 v4 = qr[d4];
            qp[d4 * 2 + 0] = pack2(v4.x, v4.y);
            qp[d4 * 2 + 1] = pack2(v4.z, v4.w);
        }
    }

    unsigned long long op[16];
    #pragma unroll
    for (int i = 0; i < 16; ++i) op[i] = 0ull;
    float mrun = -CUDART_INF_F;
    float srun = 0.f;

    for (int jt = 0; jt < 9; ++jt) {       // 9 tiles of 16 keys
        __syncthreads();                   // also covers initial K/V load
        // stage bias+mask tile: rows 0..143, cols jt*16..+15
        for (int idx = t; idx < 576; idx += 160) {
            int row = idx >> 2;
            int c4  = idx & 3;
            int gi  = row * NTOK + jt * 16 + c4 * 4;
            float4 bb = *(const float4*)(biasWH + gi);
            float4 mm = *(const float4*)(maskB + gi);
            float* dst = &BMs[row * 17 + c4 * 4];
            dst[0] = bb.x + mm.x; dst[1] = bb.y + mm.y;
            dst[2] = bb.z + mm.z; dst[3] = bb.w + mm.w;
        }
        __syncthreads();

        if (t < NTOK) {
            float st[16];
            float tmax = -CUDART_INF_F;
            #pragma unroll
            for (int jj = 0; jj < 16; ++jj) {
                const int j = jt * 16 + jj;
                const double2* kr = (const double2*)(Ks + j * DH);
                unsigned long long s0 = 0ull, s1 = 0ull, s2 = 0ull, s3 = 0ull;
                #pragma unroll
                for (int i = 0; i < 4; ++i) {
                    double2 kv0 = kr[i * 2];
                    double2 kv1 = kr[i * 2 + 1];
                    s0 = fma2(qp[i * 4 + 0], d_as_ull(kv0.x), s0);
                    s1 = fma2(qp[i * 4 + 1], d_as_ull(kv0.y), s1);
                    s2 = fma2(qp[i * 4 + 2], d_as_ull(kv1.x), s2);
                    s3 = fma2(qp[i * 4 + 3], d_as_ull(kv1.y), s3);
                }
                unsigned long long sA = add2(add2(s0, s1), add2(s2, s3));
                float2 f = unpack2(sA);
                st[jj] = (f.x + f.y) + BMs[t * 17 + jj];
                tmax = fmaxf(tmax, st[jj]);
            }
            const float mnew = fmaxf(mrun, tmax);
            const float corr = __expf(mrun - mnew);      // 0 on first tile
            srun *= corr;
            {
                const unsigned long long cp2 = pack2(corr, corr);
                #pragma unroll
                for (int i = 0; i < 16; ++i) op[i] = mul2(op[i], cp2);
            }
            #pragma unroll
            for (int jj = 0; jj < 16; ++jj) {
                const float p = __expf(st[jj] - mnew);
                srun += p;
                const unsigned long long pp = pack2(p, p);
                const double2* vr = (const double2*)(Vs + (jt * 16 + jj) * DH);
                #pragma unroll
                for (int i = 0; i < 8; ++i) {
                    double2 vv = vr[i];
                    op[i * 2 + 0] = fma2(pp, d_as_ull(vv.x), op[i * 2 + 0]);
                    op[i * 2 + 1] = fma2(pp, d_as_ull(vv.y), op[i * 2 + 1]);
                }
            }
            mrun = mnew;
        }
    }

    if (t < NTOK) {
        const float inv = 1.0f / srun;
        float* opd = g_att + ((size_t)bw * NTOK + t) * CDIM + h * DH;
        #pragma unroll
        for (int d4 = 0; d4 < 8; ++d4) {
            float2 f0 = unpack2(op[d4 * 2 + 0]);
            float2 f1 = unpack2(op[d4 * 2 + 1]);
            float4 v4;
            v4.x = f0.x * inv; v4.y = f0.y * inv;
            v4.z = f1.x * inv; v4.w = f1.y * inv;
            *(float4*)(opd + d4 * 4) = v4;
        }
    }
}

// ---------------------------------------------------------------------------
// K3: projection GEMM  g_att[M,192] @ Wp[192,192] + bp  -> d_out (FFMA2)
// ---------------------------------------------------------------------------
__global__ __launch_bounds__(256)
void proj_gemm_kernel(const float* __restrict__ Wp,
                      const float* __restrict__ bp,
                      float* __restrict__ out) {
    __shared__ float As[GBK][GBM];
    __shared__ float Bs[GBK][GBN];

    const int m0 = blockIdx.x * GBM;
    const int n0 = blockIdx.y * GBN;
    const int tid = threadIdx.x;
    const int tx = tid & 15;
    const int ty = tid >> 4;

    unsigned long long cp[4][4];
    #pragma unroll
    for (int i = 0; i < 4; ++i)
        #pragma unroll
        for (int j = 0; j < 4; ++j) cp[i][j] = 0ull;

    for (int k0 = 0; k0 < CDIM; k0 += GBK) {
        #pragma unroll
        for (int l = 0; l < 2; ++l) {
            int idx = tid + l * 256;
            int row = idx >> 2;
            int c4  = idx & 3;
            float4 a = *(const float4*)(g_att + (size_t)(m0 + row) * CDIM + k0 + c4 * 4);
            As[c4 * 4 + 0][row] = a.x;
            As[c4 * 4 + 1][row] = a.y;
            As[c4 * 4 + 2][row] = a.z;
            As[c4 * 4 + 3][row] = a.w;
        }
        {
            int krow = tid >> 4;
            int c4   = tid & 15;
            *(float4*)&Bs[krow][c4 * 4] =
                *(const float4*)(Wp + (size_t)(k0 + krow) * CDIM + n0 + c4 * 4);
        }
        __syncthreads();

        #pragma unroll
        for (int k = 0; k < GBK; ++k) {
            const double2* ap = (const double2*)&As[k][ty * 8];
            double2 a01 = ap[0], a23 = ap[1];
            unsigned long long apair[4] = {
                d_as_ull(a01.x), d_as_ull(a01.y),
                d_as_ull(a23.x), d_as_ull(a23.y)};
            float4 bb = *(const float4*)&Bs[k][tx * 4];
            unsigned long long br[4] = {
                pack2(bb.x, bb.x), pack2(bb.y, bb.y),
                pack2(bb.z, bb.z), pack2(bb.w, bb.w)};
            #pragma unroll
            for (int i = 0; i < 4; ++i)
                #pragma unroll
                for (int j = 0; j < 4; ++j)
                    cp[i][j] = fma2(apair[i], br[j], cp[i][j]);
        }
        __syncthreads();
    }

    const int cg = n0 + tx * 4;
    float4 bq = *(const float4*)(bp + cg);
    #pragma unroll
    for (int i = 0; i < 4; ++i) {
        float2 f0 = unpack2(cp[i][0]);
        float2 f1 = unpack2(cp[i][1]);
        float2 f2 = unpack2(cp[i][2]);
        float2 f3 = unpack2(cp[i][3]);
        #pragma unroll
        for (int half = 0; half < 2; ++half) {
            int m = m0 + ty * 8 + 2 * i + half;
            float4 val;
            val.x = (half ? f0.y : f0.x) + bq.x;
            val.y = (half ? f1.y : f1.x) + bq.y;
            val.z = (half ? f2.y : f2.x) + bq.z;
            val.w = (half ? f3.y : f3.x) + bq.w;
            *(float4*)(out + (size_t)m * CDIM + cg) = val;
        }
    }
}

// ---------------------------------------------------------------------------
extern "C" void kernel_launch(void* const* d_in, const int* in_sizes, int n_in,
                              void* d_out, int out_size) {
    const float* x          = (const float*)d_in[0];
    const float* mask       = (const float*)d_in[1];
    const float* w_qkv      = (const float*)d_in[2];
    const float* b_qkv      = (const float*)d_in[3];
    const float* w_proj     = (const float*)d_in[4];
    const float* b_proj     = (const float*)d_in[5];
    const float* bias_table = (const float*)d_in[6];
    const int*   pidx       = (const int*)d_in[7];
    float* out = (float*)d_out;

    build_bias_kernel<<<(BIASTOT + 255) / 256, 256>>>(bias_table, pidx);
    qkv_gemm_kernel<<<dim3(MTOT / GBM, QKVN / GBN), 256>>>(x, w_qkv, b_qkv);
    attn_kernel<<<NHEADTOT, 160>>>(mask);
    proj_gemm_kernel<<<dim3(MTOT / GBM, CDIM / GBN), 256>>>(w_proj, b_proj, out);
}